// round 6
// baseline (speedup 1.0000x reference)
#include <cuda_runtime.h>
#include <cstdint>
#include <cstddef>

#define NB 4096
#define NT 512

// z trajectory scratch, layout (B, T, 4)
__device__ float g_z[(size_t)NB * NT * 4];

__device__ __forceinline__ float tanh_fast(float a) {
    float e = __expf(2.0f * a);
    return 1.0f - __fdividef(2.0f, e + 1.0f);
}

__device__ __forceinline__ float eluf(float x) {
    return x > 0.0f ? x : (__expf(x) - 1.0f);
}

// ---------------------------------------------------------------------------
// Phase 1: reverse RNN scan + h2o + z0.  128 blocks x 256 threads.
// Block handles 32 batch elements (lane = batch). 8 warps split the 25 hidden
// units: warp w owns j = w, w+8, w+16, w+24 (j < 25). Weight columns live in
// registers. Hidden state double-buffered in shared, lane-major stride 36
// (144 B — conflict-free for LDS.128 in 8-lane phases).
// ---------------------------------------------------------------------------
__global__ void __launch_bounds__(256, 1) rnn_kernel(
    const float* __restrict__ trajs,
    const float* __restrict__ eps,
    const float* __restrict__ i2h_w,
    const float* __restrict__ i2h_b,
    const float* __restrict__ h2o_w,
    const float* __restrict__ h2o_b,
    float* __restrict__ out)
{
    __shared__ __align__(16) float hbuf[2][32][36];
    const int lane = threadIdx.x & 31;
    const int w    = threadIdx.x >> 5;
    const int b    = blockIdx.x * 32 + lane;

    // per-warp weight columns in registers
    float wr[4][27];
    float br[4];
    #pragma unroll
    for (int i = 0; i < 4; i++) {
        int j = w + 8 * i;
        if (j < 25) {
            #pragma unroll
            for (int k = 0; k < 27; k++) wr[i][k] = i2h_w[k * 25 + j];
            br[i] = i2h_b[j];
        }
    }

    for (int idx = threadIdx.x; idx < 2 * 32 * 36; idx += 256)
        ((float*)hbuf)[idx] = 0.0f;
    __syncthreads();

    const float* tb = trajs + (size_t)b * (NT * 2);
    int p = 0;
    for (int t = NT - 1; t >= 0; t--) {
        float2 xv = *(const float2*)(tb + t * 2);
        float h[25];
        #pragma unroll
        for (int q = 0; q < 6; q++) {
            float4 v = *(const float4*)&hbuf[p][lane][q * 4];
            h[q*4+0] = v.x; h[q*4+1] = v.y; h[q*4+2] = v.z; h[q*4+3] = v.w;
        }
        h[24] = hbuf[p][lane][24];

        #pragma unroll
        for (int i = 0; i < 4; i++) {
            int j = w + 8 * i;
            if (j < 25) {
                float a0 = fmaf(xv.x, wr[i][0], br[i]);
                float a1 = xv.y * wr[i][1];
                #pragma unroll
                for (int k = 0; k < 24; k += 2) {
                    a0 = fmaf(h[k],     wr[i][2 + k], a0);
                    a1 = fmaf(h[k + 1], wr[i][3 + k], a1);
                }
                a0 = fmaf(h[24], wr[i][26], a0);
                hbuf[p ^ 1][lane][j] = tanh_fast(a0 + a1);
            }
        }
        __syncthreads();
        p ^= 1;
    }

    // h2o + reparameterization, warp 0 only (32 batch lanes)
    if (w == 0) {
        float h[25];
        #pragma unroll
        for (int q = 0; q < 6; q++) {
            float4 v = *(const float4*)&hbuf[p][lane][q * 4];
            h[q*4+0] = v.x; h[q*4+1] = v.y; h[q*4+2] = v.z; h[q*4+3] = v.w;
        }
        h[24] = hbuf[p][lane][24];

        float o[8];
        #pragma unroll
        for (int c = 0; c < 8; c++) {
            float a = h2o_b[c];
            #pragma unroll
            for (int k = 0; k < 25; k++) a = fmaf(h[k], h2o_w[k * 8 + c], a);
            o[c] = a;
        }

        const size_t Z0 = (size_t)NB * NT * 2;   // offset of z0 in output
        float zc[4];
        #pragma unroll
        for (int c = 0; c < 4; c++) {
            float z = fmaf(eps[(size_t)b * 4 + c], __expf(0.5f * o[4 + c]), o[c]);
            zc[c] = z;
            out[Z0 + (size_t)b * 4 + c]                      = z;        // z0
            out[Z0 + (size_t)NB * 4 + (size_t)b * 4 + c]     = o[c];     // qz0_mean
            out[Z0 + (size_t)2 * NB * 4 + (size_t)b * 4 + c] = o[4 + c]; // qz0_logvar
        }
        *(float4*)&g_z[(size_t)b * NT * 4] = make_float4(zc[0], zc[1], zc[2], zc[3]);
    }
}

// ---------------------------------------------------------------------------
// Phase 2: RK4 ODE scan. 128 blocks x 256 threads, lane = batch.
// 8 warps split NH=20 units: warp w owns j = w, w+8 (+ w+16 if w<4).
// f3 outputs (4) computed by warps 0..3 into kb[batch][4] (one LDS.128 read).
// z replicated in every warp's registers.
// ---------------------------------------------------------------------------
__global__ void __launch_bounds__(256, 1) ode_kernel(
    const float* __restrict__ ts,
    const float* __restrict__ f1_w, const float* __restrict__ f1_b,
    const float* __restrict__ f2_w, const float* __restrict__ f2_b,
    const float* __restrict__ f3_w, const float* __restrict__ f3_b)
{
    __shared__ __align__(16) float u1buf[32][28];
    __shared__ __align__(16) float u2buf[32][28];
    __shared__ __align__(16) float kb[32][4];
    __shared__ float sdt[511];
    const int lane = threadIdx.x & 31;
    const int w    = threadIdx.x >> 5;
    const int b    = blockIdx.x * 32 + lane;

    float w1[3][4], w2[3][20], b1[3], b2[3];
    float w3[20], b3 = 0.0f;
    #pragma unroll
    for (int i = 0; i < 3; i++) {
        int j = w + 8 * i;
        if (j < 20) {
            #pragma unroll
            for (int l = 0; l < 4; l++)  w1[i][l] = f1_w[l * 20 + j];
            #pragma unroll
            for (int k = 0; k < 20; k++) w2[i][k] = f2_w[k * 20 + j];
            b1[i] = f1_b[j];
            b2[i] = f2_b[j];
        }
    }
    if (w < 4) {
        #pragma unroll
        for (int k = 0; k < 20; k++) w3[k] = f3_w[k * 4 + w];
        b3 = f3_b[w];
    }

    for (int i = threadIdx.x; i < 511; i += 256) sdt[i] = ts[i + 1] - ts[i];

    float4 zv = *(const float4*)&g_z[(size_t)b * NT * 4];
    float z[4] = {zv.x, zv.y, zv.z, zv.w};
    __syncthreads();

    for (int step = 0; step < 511; step++) {
        const float dt  = sdt[step];
        const float dt6 = dt * (1.0f / 6.0f);
        float za[4] = {z[0], z[1], z[2], z[3]};
        float zs[4] = {0.f, 0.f, 0.f, 0.f};

        #pragma unroll
        for (int s = 0; s < 4; s++) {
            // layer 1: 4 -> 20
            #pragma unroll
            for (int i = 0; i < 3; i++) {
                int j = w + 8 * i;
                if (j < 20) {
                    float a = b1[i];
                    a = fmaf(za[0], w1[i][0], a);
                    a = fmaf(za[1], w1[i][1], a);
                    a = fmaf(za[2], w1[i][2], a);
                    a = fmaf(za[3], w1[i][3], a);
                    u1buf[lane][j] = eluf(a);
                }
            }
            __syncthreads();

            // layer 2: 20 -> 20
            float u[20];
            #pragma unroll
            for (int q = 0; q < 5; q++) {
                float4 v = *(const float4*)&u1buf[lane][q * 4];
                u[q*4+0] = v.x; u[q*4+1] = v.y; u[q*4+2] = v.z; u[q*4+3] = v.w;
            }
            #pragma unroll
            for (int i = 0; i < 3; i++) {
                int j = w + 8 * i;
                if (j < 20) {
                    float a0 = b2[i], a1 = 0.0f;
                    #pragma unroll
                    for (int k = 0; k < 20; k += 2) {
                        a0 = fmaf(u[k],     w2[i][k],     a0);
                        a1 = fmaf(u[k + 1], w2[i][k + 1], a1);
                    }
                    u2buf[lane][j] = eluf(a0 + a1);
                }
            }
            __syncthreads();

            // layer 3: 20 -> 4 (warps 0..3, one output each)
            if (w < 4) {
                float uu[20];
                #pragma unroll
                for (int q = 0; q < 5; q++) {
                    float4 v = *(const float4*)&u2buf[lane][q * 4];
                    uu[q*4+0] = v.x; uu[q*4+1] = v.y; uu[q*4+2] = v.z; uu[q*4+3] = v.w;
                }
                float v0 = b3, v1 = 0.0f;
                #pragma unroll
                for (int k = 0; k < 20; k += 2) {
                    v0 = fmaf(uu[k],     w3[k],     v0);
                    v1 = fmaf(uu[k + 1], w3[k + 1], v1);
                }
                kb[lane][w] = v0 + v1;
            }
            __syncthreads();

            float4 kv = *(const float4*)&kb[lane][0];
            const float wsum = (s == 0 || s == 3) ? 1.0f : 2.0f;
            zs[0] = fmaf(wsum, kv.x, zs[0]);
            zs[1] = fmaf(wsum, kv.y, zs[1]);
            zs[2] = fmaf(wsum, kv.z, zs[2]);
            zs[3] = fmaf(wsum, kv.w, zs[3]);
            if (s < 3) {
                const float c = (s == 2) ? dt : 0.5f * dt;
                za[0] = fmaf(c, kv.x, z[0]);
                za[1] = fmaf(c, kv.y, z[1]);
                za[2] = fmaf(c, kv.z, z[2]);
                za[3] = fmaf(c, kv.w, z[3]);
            }
        }

        z[0] = fmaf(dt6, zs[0], z[0]);
        z[1] = fmaf(dt6, zs[1], z[1]);
        z[2] = fmaf(dt6, zs[2], z[2]);
        z[3] = fmaf(dt6, zs[3], z[3]);
        if (w == 0)
            *(float4*)&g_z[((size_t)b * NT + step + 1) * 4] =
                make_float4(z[0], z[1], z[2], z[3]);
    }
}

// ---------------------------------------------------------------------------
// Phase 3: decoder, fully parallel over (B, T). Coalesced read of g_z and
// coalesced write of pred_x (gid = b*T + t).
// ---------------------------------------------------------------------------
__global__ void __launch_bounds__(256) decode_kernel(
    const float* __restrict__ d1_w, const float* __restrict__ d1_b,
    const float* __restrict__ d2_w, const float* __restrict__ d2_b,
    float* __restrict__ out)
{
    __shared__ __align__(16) float s1[20][4];  // transposed d1_w
    __shared__ float sb1[20];
    __shared__ float s2[20][2];
    __shared__ float sb2[2];
    const int tid = threadIdx.x;
    if (tid < 80) {
        int j = tid >> 2, l = tid & 3;
        s1[j][l] = d1_w[l * 20 + j];
    }
    if (tid < 20) sb1[tid] = d1_b[tid];
    if (tid < 40) s2[tid >> 1][tid & 1] = d2_w[tid];
    if (tid < 2)  sb2[tid] = d2_b[tid];
    __syncthreads();

    const size_t gid = (size_t)blockIdx.x * 256 + tid;   // gid = b*T + t
    float4 zvec = *(const float4*)&g_z[gid * 4];
    float o0 = sb2[0], o1 = sb2[1];
    #pragma unroll
    for (int j = 0; j < 20; j++) {
        float4 wv = *(const float4*)&s1[j][0];
        float a = sb1[j];
        a = fmaf(zvec.x, wv.x, a);
        a = fmaf(zvec.y, wv.y, a);
        a = fmaf(zvec.z, wv.z, a);
        a = fmaf(zvec.w, wv.w, a);
        a = fmaxf(a, 0.0f);
        o0 = fmaf(a, s2[j][0], o0);
        o1 = fmaf(a, s2[j][1], o1);
    }
    *(float2*)&out[gid * 2] = make_float2(o0, o1);
}

// ---------------------------------------------------------------------------
extern "C" void kernel_launch(void* const* d_in, const int* in_sizes, int n_in,
                              void* d_out, int out_size)
{
    const float* trajs = (const float*)d_in[0];
    const float* ts    = (const float*)d_in[1];
    const float* eps   = (const float*)d_in[2];
    const float* i2h_w = (const float*)d_in[3];
    const float* i2h_b = (const float*)d_in[4];
    const float* h2o_w = (const float*)d_in[5];
    const float* h2o_b = (const float*)d_in[6];
    const float* f1_w  = (const float*)d_in[7];
    const float* f1_b  = (const float*)d_in[8];
    const float* f2_w  = (const float*)d_in[9];
    const float* f2_b  = (const float*)d_in[10];
    const float* f3_w  = (const float*)d_in[11];
    const float* f3_b  = (const float*)d_in[12];
    const float* d1_w  = (const float*)d_in[13];
    const float* d1_b  = (const float*)d_in[14];
    const float* d2_w  = (const float*)d_in[15];
    const float* d2_b  = (const float*)d_in[16];
    float* out = (float*)d_out;

    rnn_kernel<<<NB / 32, 256>>>(trajs, eps, i2h_w, i2h_b, h2o_w, h2o_b, out);
    ode_kernel<<<NB / 32, 256>>>(ts, f1_w, f1_b, f2_w, f2_b, f3_w, f3_b);
    decode_kernel<<<(NB * NT) / 256, 256>>>(d1_w, d1_b, d2_w, d2_b, out);
}

// round 7
// speedup vs baseline: 1.5180x; 1.5180x over previous
#include <cuda_runtime.h>
#include <cstdint>
#include <cstddef>

#define NB 4096
#define NT 512

// z trajectory scratch, layout (B, T, 4)
__device__ float g_z[(size_t)NB * NT * 4];

using ull = unsigned long long;

__device__ __forceinline__ ull pack2(float lo, float hi) {
    ull r; asm("mov.b64 %0, {%1, %2};" : "=l"(r) : "f"(lo), "f"(hi)); return r;
}
__device__ __forceinline__ float2 unpack2(ull v) {
    float2 r; asm("mov.b64 {%0, %1}, %2;" : "=f"(r.x), "=f"(r.y) : "l"(v)); return r;
}
// packed f32x2 FMA — PTX-only instruction on sm_10x (ptxas never auto-fuses)
__device__ __forceinline__ ull fma2(ull a, ull b, ull c) {
    ull d; asm("fma.rn.f32x2 %0, %1, %2, %3;" : "=l"(d) : "l"(a), "l"(b), "l"(c)); return d;
}

__device__ __forceinline__ float tanh_fast(float a) {
    float e = __expf(2.0f * a);
    return 1.0f - __fdividef(2.0f, e + 1.0f);
}
__device__ __forceinline__ float eluf(float x) {
    return x > 0.0f ? x : (__expf(x) - 1.0f);
}

// ---------------------------------------------------------------------------
// Phase 1: reverse RNN scan + h2o + z0.
// Octet layout: lane = (batch_sub = lane>>3, o = lane&7). Warp = 4 batches.
// Thread o owns hidden units {o, o+8, o+16} and (o==0) unit 24. Hidden state
// lives in registers, distributed across the octet; per step it is gathered
// with width-8 shuffles. No shared memory, no barriers.
// Grid 512 x 64 threads (8 batches/block) -> 1024 warps over 148 SMs.
// ---------------------------------------------------------------------------
__global__ void __launch_bounds__(64) rnn_kernel(
    const float* __restrict__ trajs,
    const float* __restrict__ eps,
    const float* __restrict__ i2h_w,
    const float* __restrict__ i2h_b,
    const float* __restrict__ h2o_w,
    const float* __restrict__ h2o_b,
    float* __restrict__ out)
{
    const int lane = threadIdx.x & 31;
    const int wrp  = threadIdx.x >> 5;
    const int o    = lane & 7;
    const int b    = blockIdx.x * 8 + wrp * 4 + (lane >> 3);

    // per-thread weight slots (zero-masked for invalid slots -> uniform flow)
    float wx0[4], wx1[4], wb[4], wh24[4];
    ull   whp[4][12];
    #pragma unroll
    for (int i = 0; i < 4; i++) {
        const bool v = (i < 3) || (o == 0);
        const int  j = v ? (o + 8 * i) : 0;
        const float s = v ? 1.0f : 0.0f;
        wx0[i] = s * i2h_w[0 * 25 + j];
        wx1[i] = s * i2h_w[1 * 25 + j];
        wb[i]  = s * i2h_b[j];
        #pragma unroll
        for (int p = 0; p < 12; p++)
            whp[i][p] = pack2(s * i2h_w[(2 + 2 * p) * 25 + j],
                              s * i2h_w[(3 + 2 * p) * 25 + j]);
        wh24[i] = s * i2h_w[26 * 25 + j];
    }

    float hown[4] = {0.f, 0.f, 0.f, 0.f};
    const float* tb = trajs + (size_t)b * (NT * 2);
    float2 xv = *(const float2*)(tb + (NT - 1) * 2);   // prefetch

    for (int t = NT - 1; t >= 0; t--) {
        const float2 xcur = xv;
        if (t > 0) xv = *(const float2*)(tb + (t - 1) * 2);  // overlap next load

        // gather full h[25] of this batch from octet registers
        ull gp[12];
        #pragma unroll
        for (int p = 0; p < 12; p++) {
            const int j0 = 2 * p, j1 = 2 * p + 1;
            float a = __shfl_sync(0xffffffffu, hown[j0 >> 3], j0 & 7, 8);
            float c = __shfl_sync(0xffffffffu, hown[j1 >> 3], j1 & 7, 8);
            gp[p] = pack2(a, c);
        }
        const float g24 = __shfl_sync(0xffffffffu, hown[3], 0, 8);

        #pragma unroll
        for (int i = 0; i < 4; i++) {
            ull acc = pack2(fmaf(xcur.x, wx0[i], wb[i]),
                            fmaf(xcur.y, wx1[i], g24 * wh24[i]));
            #pragma unroll
            for (int p = 0; p < 12; p++) acc = fma2(gp[p], whp[i][p], acc);
            const float2 lh = unpack2(acc);
            hown[i] = tanh_fast(lh.x + lh.y);
        }
    }

    // h2o: per-thread partials over owned h units, then width-8 butterfly
    float p[8];
    #pragma unroll
    for (int c = 0; c < 8; c++) p[c] = 0.f;
    #pragma unroll
    for (int i = 0; i < 4; i++) {
        const bool v = (i < 3) || (o == 0);
        const int  j = v ? (o + 8 * i) : 0;
        const float hv = v ? hown[i] : 0.f;
        #pragma unroll
        for (int c = 0; c < 8; c++)
            p[c] = fmaf(hv, h2o_w[j * 8 + c], p[c]);
    }
    #pragma unroll
    for (int d = 1; d < 8; d <<= 1) {
        #pragma unroll
        for (int c = 0; c < 8; c++)
            p[c] += __shfl_xor_sync(0xffffffffu, p[c], d, 8);
    }

    if (o == 0) {
        const size_t Z0 = (size_t)NB * NT * 2;   // offset of z0 in output
        float zc[4];
        #pragma unroll
        for (int c = 0; c < 4; c++) {
            const float m  = p[c]     + h2o_b[c];
            const float lv = p[c + 4] + h2o_b[c + 4];
            const float z  = fmaf(eps[(size_t)b * 4 + c], __expf(0.5f * lv), m);
            zc[c] = z;
            out[Z0 + (size_t)b * 4 + c]                      = z;   // z0
            out[Z0 + (size_t)NB * 4 + (size_t)b * 4 + c]     = m;   // qz0_mean
            out[Z0 + (size_t)2 * NB * 4 + (size_t)b * 4 + c] = lv;  // qz0_logvar
        }
        *(float4*)&g_z[(size_t)b * NT * 4] = make_float4(zc[0], zc[1], zc[2], zc[3]);
    }
}

// ---------------------------------------------------------------------------
// Phase 2: RK4 ODE scan, octet layout. Thread o owns units {o, o+8} and
// (o<4) o+16 of the NH=20 hidden layer. u-vectors gathered via width-8
// shuffles; k = f3 output via octet butterfly reduction. f32x2-packed layer2.
// Zero barriers, zero smem (except dt table). Grid 512 x 64.
// ---------------------------------------------------------------------------
__global__ void __launch_bounds__(64) ode_kernel(
    const float* __restrict__ ts,
    const float* __restrict__ f1_w, const float* __restrict__ f1_b,
    const float* __restrict__ f2_w, const float* __restrict__ f2_b,
    const float* __restrict__ f3_w, const float* __restrict__ f3_b)
{
    __shared__ float sdt[NT - 1];
    const int lane = threadIdx.x & 31;
    const int wrp  = threadIdx.x >> 5;
    const int o    = lane & 7;
    const int b    = blockIdx.x * 8 + wrp * 4 + (lane >> 3);

    float w1r[3][4], b1r[3], b2r[3];
    ull   w2p[3][10], w3p[3][2];
    #pragma unroll
    for (int i = 0; i < 3; i++) {
        const bool v = (i < 2) || (o < 4);
        const int  j = v ? (o + 8 * i) : 0;
        const float s = v ? 1.0f : 0.0f;
        #pragma unroll
        for (int l = 0; l < 4; l++) w1r[i][l] = s * f1_w[l * 20 + j];
        b1r[i] = s * f1_b[j];
        b2r[i] = s * f2_b[j];
        #pragma unroll
        for (int p = 0; p < 10; p++)
            w2p[i][p] = pack2(s * f2_w[(2 * p) * 20 + j],
                              s * f2_w[(2 * p + 1) * 20 + j]);
        w3p[i][0] = pack2(s * f3_w[j * 4 + 0], s * f3_w[j * 4 + 1]);
        w3p[i][1] = pack2(s * f3_w[j * 4 + 2], s * f3_w[j * 4 + 3]);
    }
    const float fb[4] = {f3_b[0], f3_b[1], f3_b[2], f3_b[3]};

    for (int i = threadIdx.x; i < NT - 1; i += 64) sdt[i] = ts[i + 1] - ts[i];

    const float4 zv = *(const float4*)&g_z[(size_t)b * NT * 4];
    float z[4] = {zv.x, zv.y, zv.z, zv.w};
    __syncthreads();

    for (int step = 0; step < NT - 1; step++) {
        const float dt = sdt[step];
        float za[4] = {z[0], z[1], z[2], z[3]};
        float zs[4] = {0.f, 0.f, 0.f, 0.f};

        #pragma unroll
        for (int s4 = 0; s4 < 4; s4++) {
            // layer 1: 4 -> 20 (own units only; za replicated per thread)
            float u1own[3];
            #pragma unroll
            for (int i = 0; i < 3; i++) {
                float a = b1r[i];
                a = fmaf(za[0], w1r[i][0], a);
                a = fmaf(za[1], w1r[i][1], a);
                a = fmaf(za[2], w1r[i][2], a);
                a = fmaf(za[3], w1r[i][3], a);
                u1own[i] = eluf(a);
            }
            // gather u1[20] from octet registers, packed pairs
            ull up[10];
            #pragma unroll
            for (int p = 0; p < 10; p++) {
                const int j0 = 2 * p, j1 = 2 * p + 1;
                float a = __shfl_sync(0xffffffffu, u1own[j0 >> 3], j0 & 7, 8);
                float c = __shfl_sync(0xffffffffu, u1own[j1 >> 3], j1 & 7, 8);
                up[p] = pack2(a, c);
            }
            // layer 2: 20 -> 20, f32x2 packed
            float u2own[3];
            #pragma unroll
            for (int i = 0; i < 3; i++) {
                ull acc = pack2(b2r[i], 0.f);
                #pragma unroll
                for (int p = 0; p < 10; p++) acc = fma2(up[p], w2p[i][p], acc);
                const float2 lh = unpack2(acc);
                u2own[i] = eluf(lh.x + lh.y);
            }
            // layer 3: 20 -> 4 via partials + octet butterfly
            ull p01 = pack2(0.f, 0.f), p23 = pack2(0.f, 0.f);
            #pragma unroll
            for (int i = 0; i < 3; i++) {
                const ull uu = pack2(u2own[i], u2own[i]);
                p01 = fma2(uu, w3p[i][0], p01);
                p23 = fma2(uu, w3p[i][1], p23);
            }
            const float2 a01 = unpack2(p01), a23 = unpack2(p23);
            float kk[4] = {a01.x, a01.y, a23.x, a23.y};
            #pragma unroll
            for (int d = 1; d < 8; d <<= 1) {
                #pragma unroll
                for (int c = 0; c < 4; c++)
                    kk[c] += __shfl_xor_sync(0xffffffffu, kk[c], d, 8);
            }
            #pragma unroll
            for (int c = 0; c < 4; c++) kk[c] += fb[c];

            const float wsum = (s4 == 0 || s4 == 3) ? 1.0f : 2.0f;
            #pragma unroll
            for (int c = 0; c < 4; c++) zs[c] = fmaf(wsum, kk[c], zs[c]);
            if (s4 < 3) {
                const float cc = (s4 == 2) ? dt : 0.5f * dt;
                #pragma unroll
                for (int c = 0; c < 4; c++) za[c] = fmaf(cc, kk[c], z[c]);
            }
        }

        const float dt6 = dt * (1.0f / 6.0f);
        #pragma unroll
        for (int c = 0; c < 4; c++) z[c] = fmaf(dt6, zs[c], z[c]);
        if (o == 0)
            *(float4*)&g_z[((size_t)b * NT + step + 1) * 4] =
                make_float4(z[0], z[1], z[2], z[3]);
    }
}

// ---------------------------------------------------------------------------
// Phase 3: decoder, fully parallel over (B, T). Coalesced read of g_z and
// coalesced write of pred_x (gid = b*T + t).
// ---------------------------------------------------------------------------
__global__ void __launch_bounds__(256) decode_kernel(
    const float* __restrict__ d1_w, const float* __restrict__ d1_b,
    const float* __restrict__ d2_w, const float* __restrict__ d2_b,
    float* __restrict__ out)
{
    __shared__ __align__(16) float s1[20][4];  // transposed d1_w
    __shared__ float sb1[20];
    __shared__ float s2[20][2];
    __shared__ float sb2[2];
    const int tid = threadIdx.x;
    if (tid < 80) {
        int j = tid >> 2, l = tid & 3;
        s1[j][l] = d1_w[l * 20 + j];
    }
    if (tid < 20) sb1[tid] = d1_b[tid];
    if (tid < 40) s2[tid >> 1][tid & 1] = d2_w[tid];
    if (tid < 2)  sb2[tid] = d2_b[tid];
    __syncthreads();

    const size_t gid = (size_t)blockIdx.x * 256 + tid;   // gid = b*T + t
    const float4 zvec = *(const float4*)&g_z[gid * 4];
    float o0 = sb2[0], o1 = sb2[1];
    #pragma unroll
    for (int j = 0; j < 20; j++) {
        const float4 wv = *(const float4*)&s1[j][0];
        float a = sb1[j];
        a = fmaf(zvec.x, wv.x, a);
        a = fmaf(zvec.y, wv.y, a);
        a = fmaf(zvec.z, wv.z, a);
        a = fmaf(zvec.w, wv.w, a);
        a = fmaxf(a, 0.0f);
        o0 = fmaf(a, s2[j][0], o0);
        o1 = fmaf(a, s2[j][1], o1);
    }
    *(float2*)&out[gid * 2] = make_float2(o0, o1);
}

// ---------------------------------------------------------------------------
extern "C" void kernel_launch(void* const* d_in, const int* in_sizes, int n_in,
                              void* d_out, int out_size)
{
    const float* trajs = (const float*)d_in[0];
    const float* ts    = (const float*)d_in[1];
    const float* eps   = (const float*)d_in[2];
    const float* i2h_w = (const float*)d_in[3];
    const float* i2h_b = (const float*)d_in[4];
    const float* h2o_w = (const float*)d_in[5];
    const float* h2o_b = (const float*)d_in[6];
    const float* f1_w  = (const float*)d_in[7];
    const float* f1_b  = (const float*)d_in[8];
    const float* f2_w  = (const float*)d_in[9];
    const float* f2_b  = (const float*)d_in[10];
    const float* f3_w  = (const float*)d_in[11];
    const float* f3_b  = (const float*)d_in[12];
    const float* d1_w  = (const float*)d_in[13];
    const float* d1_b  = (const float*)d_in[14];
    const float* d2_w  = (const float*)d_in[15];
    const float* d2_b  = (const float*)d_in[16];
    float* out = (float*)d_out;

    rnn_kernel<<<NB / 8, 64>>>(trajs, eps, i2h_w, i2h_b, h2o_w, h2o_b, out);
    ode_kernel<<<NB / 8, 64>>>(ts, f1_w, f1_b, f2_w, f2_b, f3_w, f3_b);
    decode_kernel<<<(NB * NT) / 256, 256>>>(d1_w, d1_b, d2_w, d2_b, out);
}

// round 8
// speedup vs baseline: 1.5214x; 1.0022x over previous
#include <cuda_runtime.h>
#include <cstdint>
#include <cstddef>

#define NB 4096
#define NT 512

// z trajectory scratch, layout (B, T, 4)
__device__ float g_z[(size_t)NB * NT * 4];

using ull = unsigned long long;

__device__ __forceinline__ ull pack2(float lo, float hi) {
    ull r; asm("mov.b64 %0, {%1, %2};" : "=l"(r) : "f"(lo), "f"(hi)); return r;
}
__device__ __forceinline__ float2 unpack2(ull v) {
    float2 r; asm("mov.b64 {%0, %1}, %2;" : "=f"(r.x), "=f"(r.y) : "l"(v)); return r;
}
// packed f32x2 FMA / ADD — PTX-only on sm_10x
__device__ __forceinline__ ull fma2(ull a, ull b, ull c) {
    ull d; asm("fma.rn.f32x2 %0, %1, %2, %3;" : "=l"(d) : "l"(a), "l"(b), "l"(c)); return d;
}
__device__ __forceinline__ ull add2(ull a, ull b) {
    ull d; asm("add.rn.f32x2 %0, %1, %2;" : "=l"(d) : "l"(a), "l"(b)); return d;
}
__device__ __forceinline__ ull shflx2(ull v, int d, int w) {
    float2 f = unpack2(v);
    f.x = __shfl_xor_sync(0xffffffffu, f.x, d, w);
    f.y = __shfl_xor_sync(0xffffffffu, f.y, d, w);
    return pack2(f.x, f.y);
}

__device__ __forceinline__ float tanh_fast(float a) {
    float e = __expf(2.0f * a);
    return 1.0f - __fdividef(2.0f, e + 1.0f);
}
__device__ __forceinline__ float eluf(float x) {
    return x > 0.0f ? x : (__expf(x) - 1.0f);
}

// ---------------------------------------------------------------------------
// Phase 1: reverse RNN scan + h2o + z0.  ILP-2 octet layout.
// lane = (octet s = lane>>3, o = lane&7). Each octet serves TWO batches
// (2*s, 2*s+1 within the warp's 8); each thread carries both batches' state
// so the two dependency chains interleave and hide SHFL/MUFU latency.
// Weights (register-resident) are shared across the two batches.
// Grid 256 x 64 threads -> 512 warps.
// ---------------------------------------------------------------------------
__global__ void __launch_bounds__(64) rnn_kernel(
    const float* __restrict__ trajs,
    const float* __restrict__ eps,
    const float* __restrict__ i2h_w,
    const float* __restrict__ i2h_b,
    const float* __restrict__ h2o_w,
    const float* __restrict__ h2o_b,
    float* __restrict__ out)
{
    const int lane = threadIdx.x & 31;
    const int wrp  = threadIdx.x >> 5;
    const int o    = lane & 7;
    const int s    = lane >> 3;
    const int b0   = blockIdx.x * 16 + wrp * 8 + s * 2;   // batches b0, b0+1

    // per-thread weight slots (zero-masked invalid slots -> uniform flow)
    float wx0[4], wx1[4], wb[4], wh24[4];
    ull   whp[4][12];
    #pragma unroll
    for (int i = 0; i < 4; i++) {
        const bool v = (i < 3) || (o == 0);
        const int  j = v ? (o + 8 * i) : 0;
        const float sc = v ? 1.0f : 0.0f;
        wx0[i] = sc * i2h_w[0 * 25 + j];
        wx1[i] = sc * i2h_w[1 * 25 + j];
        wb[i]  = sc * i2h_b[j];
        #pragma unroll
        for (int p = 0; p < 12; p++)
            whp[i][p] = pack2(sc * i2h_w[(2 + 2 * p) * 25 + j],
                              sc * i2h_w[(3 + 2 * p) * 25 + j]);
        wh24[i] = sc * i2h_w[26 * 25 + j];
    }

    float hown[2][4] = {{0.f,0.f,0.f,0.f},{0.f,0.f,0.f,0.f}};
    const float* tb0 = trajs + (size_t)b0 * (NT * 2);
    const float* tb1 = trajs + (size_t)(b0 + 1) * (NT * 2);
    float2 xv0 = *(const float2*)(tb0 + (NT - 1) * 2);
    float2 xv1 = *(const float2*)(tb1 + (NT - 1) * 2);

    for (int t = NT - 1; t >= 0; t--) {
        const float2 xc0 = xv0, xc1 = xv1;
        if (t > 0) {
            xv0 = *(const float2*)(tb0 + (t - 1) * 2);
            xv1 = *(const float2*)(tb1 + (t - 1) * 2);
        }

        // gather h[25] for both batches (independent shuffle streams)
        ull gp[2][12];
        float g24[2];
        #pragma unroll
        for (int p = 0; p < 12; p++) {
            const int j0 = 2 * p, j1 = 2 * p + 1;
            float a0 = __shfl_sync(0xffffffffu, hown[0][j0 >> 3], j0 & 7, 8);
            float c0 = __shfl_sync(0xffffffffu, hown[0][j1 >> 3], j1 & 7, 8);
            float a1 = __shfl_sync(0xffffffffu, hown[1][j0 >> 3], j0 & 7, 8);
            float c1 = __shfl_sync(0xffffffffu, hown[1][j1 >> 3], j1 & 7, 8);
            gp[0][p] = pack2(a0, c0);
            gp[1][p] = pack2(a1, c1);
        }
        g24[0] = __shfl_sync(0xffffffffu, hown[0][3], 0, 8);
        g24[1] = __shfl_sync(0xffffffffu, hown[1][3], 0, 8);

        #pragma unroll
        for (int i = 0; i < 4; i++) {
            // batch 0
            ull aA0 = pack2(fmaf(xc0.x, wx0[i], wb[i]),
                            fmaf(xc0.y, wx1[i], g24[0] * wh24[i]));
            ull aB0 = pack2(0.f, 0.f);
            // batch 1 (interleaved chain)
            ull aA1 = pack2(fmaf(xc1.x, wx0[i], wb[i]),
                            fmaf(xc1.y, wx1[i], g24[1] * wh24[i]));
            ull aB1 = pack2(0.f, 0.f);
            #pragma unroll
            for (int p = 0; p < 6; p++) {
                aA0 = fma2(gp[0][p],     whp[i][p],     aA0);
                aB0 = fma2(gp[0][p + 6], whp[i][p + 6], aB0);
                aA1 = fma2(gp[1][p],     whp[i][p],     aA1);
                aB1 = fma2(gp[1][p + 6], whp[i][p + 6], aB1);
            }
            const float2 l0 = unpack2(add2(aA0, aB0));
            const float2 l1 = unpack2(add2(aA1, aB1));
            hown[0][i] = tanh_fast(l0.x + l0.y);
            hown[1][i] = tanh_fast(l1.x + l1.y);
        }
    }

    // h2o + reparameterization for both batches
    #pragma unroll
    for (int bb = 0; bb < 2; bb++) {
        const int b = b0 + bb;
        float p[8];
        #pragma unroll
        for (int c = 0; c < 8; c++) p[c] = 0.f;
        #pragma unroll
        for (int i = 0; i < 4; i++) {
            const bool v = (i < 3) || (o == 0);
            const int  j = v ? (o + 8 * i) : 0;
            const float hv = v ? hown[bb][i] : 0.f;
            #pragma unroll
            for (int c = 0; c < 8; c++)
                p[c] = fmaf(hv, h2o_w[j * 8 + c], p[c]);
        }
        #pragma unroll
        for (int d = 1; d < 8; d <<= 1) {
            #pragma unroll
            for (int c = 0; c < 8; c++)
                p[c] += __shfl_xor_sync(0xffffffffu, p[c], d, 8);
        }
        if (o == 0) {
            const size_t Z0 = (size_t)NB * NT * 2;
            float zc[4];
            #pragma unroll
            for (int c = 0; c < 4; c++) {
                const float m  = p[c]     + h2o_b[c];
                const float lv = p[c + 4] + h2o_b[c + 4];
                const float z  = fmaf(eps[(size_t)b * 4 + c], __expf(0.5f * lv), m);
                zc[c] = z;
                out[Z0 + (size_t)b * 4 + c]                      = z;
                out[Z0 + (size_t)NB * 4 + (size_t)b * 4 + c]     = m;
                out[Z0 + (size_t)2 * NB * 4 + (size_t)b * 4 + c] = lv;
            }
            *(float4*)&g_z[(size_t)b * NT * 4] =
                make_float4(zc[0], zc[1], zc[2], zc[3]);
        }
    }
}

// ---------------------------------------------------------------------------
// Phase 2: RK4 ODE scan, QUAD layout. lane = (q = lane>>2 -> batch, o =
// lane&3 -> unit owner). Thread o owns units j = o + 4i, i=0..4 (exact fit,
// no padding). 8 batches/warp, 512 warps. Width-4 shuffles gather u vectors
// (one warp-SHFL serves all 8 batches). Layer-2 split accumulators, packed
// f32x2 state updates, 2-stage packed butterfly for k.
// ---------------------------------------------------------------------------
__global__ void __launch_bounds__(64) ode_kernel(
    const float* __restrict__ ts,
    const float* __restrict__ f1_w, const float* __restrict__ f1_b,
    const float* __restrict__ f2_w, const float* __restrict__ f2_b,
    const float* __restrict__ f3_w, const float* __restrict__ f3_b)
{
    __shared__ float sdt[NT - 1];
    const int lane = threadIdx.x & 31;
    const int wrp  = threadIdx.x >> 5;
    const int o    = lane & 3;
    const int q    = lane >> 2;
    const int b    = blockIdx.x * 16 + wrp * 8 + q;

    float w1r[5][4], b1r[5], b2r[5];
    ull   w2p[5][10], w3a[5], w3b[5];
    #pragma unroll
    for (int i = 0; i < 5; i++) {
        const int j = o + 4 * i;
        #pragma unroll
        for (int l = 0; l < 4; l++) w1r[i][l] = f1_w[l * 20 + j];
        b1r[i] = f1_b[j];
        b2r[i] = f2_b[j];
        #pragma unroll
        for (int p = 0; p < 10; p++)
            w2p[i][p] = pack2(f2_w[(2 * p) * 20 + j], f2_w[(2 * p + 1) * 20 + j]);
        w3a[i] = pack2(f3_w[j * 4 + 0], f3_w[j * 4 + 1]);
        w3b[i] = pack2(f3_w[j * 4 + 2], f3_w[j * 4 + 3]);
    }
    const ull fb01 = pack2(f3_b[0], f3_b[1]);
    const ull fb23 = pack2(f3_b[2], f3_b[3]);

    for (int i = threadIdx.x; i < NT - 1; i += 64) sdt[i] = ts[i + 1] - ts[i];

    const float4 zv = *(const float4*)&g_z[(size_t)b * NT * 4];
    ull z01 = pack2(zv.x, zv.y), z23 = pack2(zv.z, zv.w);
    __syncthreads();

    for (int step = 0; step < NT - 1; step++) {
        const float dt = sdt[step];
        ull za01 = z01, za23 = z23;
        ull zs01 = pack2(0.f, 0.f), zs23 = pack2(0.f, 0.f);

        #pragma unroll
        for (int s4 = 0; s4 < 4; s4++) {
            const float2 a01 = unpack2(za01), a23 = unpack2(za23);
            // layer 1: 4 -> 20 (5 own units, ILP 5)
            float u1own[5];
            #pragma unroll
            for (int i = 0; i < 5; i++) {
                float a = b1r[i];
                a = fmaf(a01.x, w1r[i][0], a);
                a = fmaf(a01.y, w1r[i][1], a);
                a = fmaf(a23.x, w1r[i][2], a);
                a = fmaf(a23.y, w1r[i][3], a);
                u1own[i] = eluf(a);
            }
            // gather u1[20] via width-4 shuffles (serves all 8 batches at once)
            ull up[10];
            #pragma unroll
            for (int p = 0; p < 10; p++) {
                const int j0 = 2 * p, j1 = 2 * p + 1;
                float x0 = __shfl_sync(0xffffffffu, u1own[j0 >> 2], j0 & 3, 4);
                float x1 = __shfl_sync(0xffffffffu, u1own[j1 >> 2], j1 & 3, 4);
                up[p] = pack2(x0, x1);
            }
            // layer 2: 20 -> 20, split dual accumulators
            float u2own[5];
            #pragma unroll
            for (int i = 0; i < 5; i++) {
                ull aA = pack2(b2r[i], 0.f);
                ull aB = pack2(0.f, 0.f);
                #pragma unroll
                for (int p = 0; p < 5; p++) {
                    aA = fma2(up[p],     w2p[i][p],     aA);
                    aB = fma2(up[p + 5], w2p[i][p + 5], aB);
                }
                const float2 lh = unpack2(add2(aA, aB));
                u2own[i] = eluf(lh.x + lh.y);
            }
            // layer 3: 20 -> 4, packed partials + 2-stage width-4 butterfly
            ull k01 = pack2(0.f, 0.f), k23 = pack2(0.f, 0.f);
            #pragma unroll
            for (int i = 0; i < 5; i++) {
                const ull uu = pack2(u2own[i], u2own[i]);
                k01 = fma2(uu, w3a[i], k01);
                k23 = fma2(uu, w3b[i], k23);
            }
            k01 = add2(k01, shflx2(k01, 1, 4));
            k23 = add2(k23, shflx2(k23, 1, 4));
            k01 = add2(k01, shflx2(k01, 2, 4));
            k23 = add2(k23, shflx2(k23, 2, 4));
            k01 = add2(k01, fb01);
            k23 = add2(k23, fb23);

            const float wf = (s4 == 0 || s4 == 3) ? 1.0f : 2.0f;
            const ull ws = pack2(wf, wf);
            zs01 = fma2(ws, k01, zs01);
            zs23 = fma2(ws, k23, zs23);
            if (s4 < 3) {
                const float cc = (s4 == 2) ? dt : 0.5f * dt;
                const ull cp = pack2(cc, cc);
                za01 = fma2(cp, k01, z01);
                za23 = fma2(cp, k23, z23);
            }
        }

        const float dt6 = dt * (1.0f / 6.0f);
        const ull d6 = pack2(dt6, dt6);
        z01 = fma2(d6, zs01, z01);
        z23 = fma2(d6, zs23, z23);
        if (o == 0) {
            const float2 r01 = unpack2(z01), r23 = unpack2(z23);
            *(float4*)&g_z[((size_t)b * NT + step + 1) * 4] =
                make_float4(r01.x, r01.y, r23.x, r23.y);
        }
    }
}

// ---------------------------------------------------------------------------
// Phase 3: decoder, fully parallel over (B, T). Coalesced.
// ---------------------------------------------------------------------------
__global__ void __launch_bounds__(256) decode_kernel(
    const float* __restrict__ d1_w, const float* __restrict__ d1_b,
    const float* __restrict__ d2_w, const float* __restrict__ d2_b,
    float* __restrict__ out)
{
    __shared__ __align__(16) float s1[20][4];
    __shared__ float sb1[20];
    __shared__ float s2[20][2];
    __shared__ float sb2[2];
    const int tid = threadIdx.x;
    if (tid < 80) {
        int j = tid >> 2, l = tid & 3;
        s1[j][l] = d1_w[l * 20 + j];
    }
    if (tid < 20) sb1[tid] = d1_b[tid];
    if (tid < 40) s2[tid >> 1][tid & 1] = d2_w[tid];
    if (tid < 2)  sb2[tid] = d2_b[tid];
    __syncthreads();

    const size_t gid = (size_t)blockIdx.x * 256 + tid;
    const float4 zvec = *(const float4*)&g_z[gid * 4];
    float o0 = sb2[0], o1 = sb2[1];
    #pragma unroll
    for (int j = 0; j < 20; j++) {
        const float4 wv = *(const float4*)&s1[j][0];
        float a = sb1[j];
        a = fmaf(zvec.x, wv.x, a);
        a = fmaf(zvec.y, wv.y, a);
        a = fmaf(zvec.z, wv.z, a);
        a = fmaf(zvec.w, wv.w, a);
        a = fmaxf(a, 0.0f);
        o0 = fmaf(a, s2[j][0], o0);
        o1 = fmaf(a, s2[j][1], o1);
    }
    *(float2*)&out[gid * 2] = make_float2(o0, o1);
}

// ---------------------------------------------------------------------------
extern "C" void kernel_launch(void* const* d_in, const int* in_sizes, int n_in,
                              void* d_out, int out_size)
{
    const float* trajs = (const float*)d_in[0];
    const float* ts    = (const float*)d_in[1];
    const float* eps   = (const float*)d_in[2];
    const float* i2h_w = (const float*)d_in[3];
    const float* i2h_b = (const float*)d_in[4];
    const float* h2o_w = (const float*)d_in[5];
    const float* h2o_b = (const float*)d_in[6];
    const float* f1_w  = (const float*)d_in[7];
    const float* f1_b  = (const float*)d_in[8];
    const float* f2_w  = (const float*)d_in[9];
    const float* f2_b  = (const float*)d_in[10];
    const float* f3_w  = (const float*)d_in[11];
    const float* f3_b  = (const float*)d_in[12];
    const float* d1_w  = (const float*)d_in[13];
    const float* d1_b  = (const float*)d_in[14];
    const float* d2_w  = (const float*)d_in[15];
    const float* d2_b  = (const float*)d_in[16];
    float* out = (float*)d_out;

    rnn_kernel<<<NB / 16, 64>>>(trajs, eps, i2h_w, i2h_b, h2o_w, h2o_b, out);
    ode_kernel<<<NB / 16, 64>>>(ts, f1_w, f1_b, f2_w, f2_b, f3_w, f3_b);
    decode_kernel<<<(NB * NT) / 256, 256>>>(d1_w, d1_b, d2_w, d2_b, out);
}